// round 8
// baseline (speedup 1.0000x reference)
#include <cuda_runtime.h>
#include <math.h>

// Problem constants (fixed by reference: IMG=2048, strides 8/16/32, B=2, M=128)
#define L3 65536
#define L4 16384
#define L5 4096
#define LTOT (L3 + L4 + L5)   // 86016
#define NB 2
#define NGT 128

// Single-wave fused kernel: 84 blocks x 256 threads, 8 locations/thread
// (2048 locs/block; 65536, 81920, 86016 are all multiples of 2048 -> each
// block is (batch, level)-uniform; 8-aligned col runs stay inside one grid
// row at every level since n >= 64).
__global__ __launch_bounds__(256) void fcos_fused(
    const float* __restrict__ gt,      // (B, 128, 5)
    const float* __restrict__ p3,      // (B, L3, 4)
    const float* __restrict__ p4,
    const float* __restrict__ p5,
    float* __restrict__ out)           // (B, LTOT, 9)
{
    __shared__ float4 sbox[NGT];                 // {x0,y0,x1,y1} per slot
    __shared__ unsigned long long skey[NGT];     // packed winner key
    __shared__ int swc[4];                       // per-warp shortlist count

    const int tid   = threadIdx.x;               // 0..255
    const int gbase = blockIdx.x * 2048;
    const int b     = (gbase >= LTOT) ? 1 : 0;
    const int locb  = gbase - b * LTOT;

    // Level selection — uniform per block.
    float s, lo, hi;
    const float* pred;
    int nshift, off;
    if (locb < L3) {
        s = 8.0f;  lo = 0.0f;   hi = 64.0f;
        pred = p3 + (size_t)b * L3 * 4; nshift = 8; off = 0;          // n=256
    } else if (locb < L3 + L4) {
        s = 16.0f; lo = 64.0f;  hi = 128.0f;
        pred = p4 + (size_t)b * L4 * 4; nshift = 7; off = L3;         // n=128
    } else {
        s = 32.0f; lo = 128.0f; hi = INFINITY;
        pred = p5 + (size_t)b * L5 * 4; nshift = 6; off = L3 + L4;    // n=64
    }
    const int nmask = (1 << nshift) - 1;

    const int l0   = locb - off;             // level-local block start
    const int lidx = l0 + 8 * tid;           // first of this thread's 8 locs
    const int row  = lidx >> nshift;
    const int col  = lidx & nmask;           // 8-aligned -> all 8 in one row
    // Analytic coords: (k+0.5)*2^m exact in fp32 -> bitwise equal to ref.
    const float y   = ((float)row + 0.5f) * s;
    const float x0c = ((float)col + 0.5f) * s;

    // Analytic y-band of the whole block.
    const float ylo = ((float)(l0 >> nshift)          + 0.5f) * s;
    const float yhi = ((float)((l0 + 2047) >> nshift) + 0.5f) * s;

    // Prefetch predictions (8 x LDG.128, independent of the barrier).
    float4 pr[8];
    #pragma unroll
    for (int q = 0; q < 8; ++q)
        pr[q] = reinterpret_cast<const float4*>(pred)[lidx + q];

    // ---- Phase 1: warps 0..3 build compacted per-warp shortlists ----
    if (tid < NGT) {
        const int w    = tid >> 5;
        const int lane = tid & 31;
        const float* g = gt + ((size_t)(b * NGT + tid)) * 5;
        const float bx0 = g[0], by0 = g[1], bx1 = g[2], by1 = g[3];
        // Valid-center window: x in (max(x0,x1-hi), min(x1,x0+hi)), same in y.
        const float xl = fmaxf(bx0, bx1 - hi), xh = fminf(bx1, bx0 + hi);
        const float yl = fmaxf(by0, by1 - hi), yh = fminf(by1, by0 + hi);
        const bool cand = (xh > xl) && (yh > ylo) && (yl < yhi);
        const unsigned mask = __ballot_sync(0xFFFFFFFFu, cand);
        if (cand) {
            const int slot = (w << 5) + __popc(mask & ((1u << lane) - 1u));
            sbox[slot] = make_float4(bx0, by0, bx1, by1);
            const float mmv = 1e8f - (bx1 - bx0) * (by1 - by0);
            // mm bits (positive float, order-isomorphic) | first-index tie | slot.
            skey[slot] = ((unsigned long long)__float_as_uint(mmv) << 32) |
                         ((unsigned)(NGT - 1 - tid) << 8) | (unsigned)slot;
        }
        if (lane == 0) swc[w] = __popc(mask);
    }
    __syncthreads();

    // ---- Phase 2: scan compacted segments, 8 x-positions per entry ----
    unsigned long long best[8] = {0ull,0ull,0ull,0ull,0ull,0ull,0ull,0ull};
    #pragma unroll
    for (int w = 0; w < 4; ++w) {
        const int cnt  = swc[w];
        const int base = w << 5;
        for (int k = 0; k < cnt; ++k) {
            const float4 bx = sbox[base + k];
            const float t  = y - bx.y;
            const float bt = bx.w - y;
            const float vmin = fminf(t, bt);
            const float vmax = fmaxf(t, bt);
            const unsigned long long key = skey[base + k];
            #pragma unroll
            for (int q = 0; q < 8; ++q) {
                const float x = x0c + (float)q * s;
                const float l = x - bx.x, r = bx.z - x;
                const float pmin = fminf(fminf(l, r), vmin);
                const float pmax = fmaxf(fmaxf(l, r), vmax);
                if (pmin > 0.0f && pmax > lo && pmax < hi && key > best[q])
                    best[q] = key;
            }
        }
    }

    // ---- Phase 3: finalize, two groups of 4 locations (caps live regs) ----
    const float inv_s = 1.0f / s;
    const size_t i0 = (size_t)b * LTOT + off + lidx;

    #pragma unroll
    for (int gq = 0; gq < 2; ++gq) {
        float v[36];
        #pragma unroll
        for (int q = 0; q < 4; ++q) {
            const int qq = gq * 4 + q;
            const float x = x0c + (float)qq * s;
            float* o = v + q * 9;
            if (best[qq] == 0ull) {
                o[0] = o[1] = o[2] = o[3] = -1.0f;
                o[4] = -1.0f;
            } else {
                const float4 bx = sbox[best[qq] & 0xFFu];
                const float d0 = (x - bx.x) * inv_s;
                const float d1 = (y - bx.y) * inv_s;
                const float d2 = (bx.z - x) * inv_s;
                const float d3 = (bx.w - y) * inv_s;
                const float lrmin = fminf(d0, d2), lrmax = fmaxf(d0, d2);
                const float tbmin = fminf(d1, d3), tbmax = fmaxf(d1, d3);
                const float ratio = fminf(lrmin, tbmin) /
                                    (fmaxf(lrmax, tbmax) + 1e-6f);
                o[0] = d0; o[1] = d1; o[2] = d2; o[3] = d3;
                o[4] = sqrtf(fmaxf(ratio, 0.0f));
            }
            const float4 p = pr[qq];
            o[5] = fmaxf(x - fmaxf(p.x, 0.0f) * s, 0.0f);
            o[6] = fmaxf(y - fmaxf(p.y, 0.0f) * s, 0.0f);
            o[7] = fmaxf(x + fmaxf(p.z, 0.0f) * s, 0.0f);
            o[8] = fmaxf(y + fmaxf(p.w, 0.0f) * s, 0.0f);
        }
        // 36 contiguous floats, 16B-aligned -> 9 x STG.128.
        float4* o4 = reinterpret_cast<float4*>(out + (i0 + gq * 4) * 9);
        #pragma unroll
        for (int k = 0; k < 9; ++k)
            o4[k] = make_float4(v[4*k], v[4*k+1], v[4*k+2], v[4*k+3]);
    }
}

extern "C" void kernel_launch(void* const* d_in, const int* in_sizes, int n_in,
                              void* d_out, int out_size) {
    const float* gt = (const float*)d_in[3];
    const float* p3 = (const float*)d_in[4];
    const float* p4 = (const float*)d_in[5];
    const float* p5 = (const float*)d_in[6];
    float* out = (float*)d_out;

    const int blocks = NB * LTOT / 2048;   // 84 — single wave on 148 SMs
    fcos_fused<<<blocks, 256>>>(gt, p3, p4, p5, out);
}

// round 9
// speedup vs baseline: 2.5389x; 2.5389x over previous
#include <cuda_runtime.h>
#include <math.h>

// Problem constants (fixed by reference: IMG=2048, strides 8/16/32, B=2, M=128)
#define L3 65536
#define L4 16384
#define L5 4096
#define LTOT (L3 + L4 + L5)   // 86016
#define NB 2
#define NGT 128

// Fused kernel: 672 blocks x 128 threads, 2 locations/thread (256 locs/block).
// All level/batch boundaries are multiples of 256 -> each block is
// (batch, level)-uniform. 256 locs/block = exactly 1 grid row at p3,
// 2 rows at p4, 4 rows at p5 -> tight y-band, tiny shortlist.
__global__ __launch_bounds__(128) void fcos_fused(
    const float* __restrict__ gt,      // (B, 128, 5)
    const float* __restrict__ p3,      // (B, L3, 4)
    const float* __restrict__ p4,
    const float* __restrict__ p5,
    float* __restrict__ out)           // (B, LTOT, 9)
{
    __shared__ float4 sbox[NGT];                 // {x0,y0,x1,y1} per slot
    __shared__ unsigned long long skey[NGT];     // packed winner key
    __shared__ int swc[4];                       // per-warp shortlist count

    const int tid   = threadIdx.x;               // 0..127
    const int gbase = blockIdx.x * 256;
    const int b     = (gbase >= LTOT) ? 1 : 0;
    const int locb  = gbase - b * LTOT;

    // Level selection — uniform per block.
    float s, lo, hi;
    const float* pred;
    int nshift, off;
    if (locb < L3) {
        s = 8.0f;  lo = 0.0f;   hi = 64.0f;
        pred = p3 + (size_t)b * L3 * 4; nshift = 8; off = 0;          // n=256
    } else if (locb < L3 + L4) {
        s = 16.0f; lo = 64.0f;  hi = 128.0f;
        pred = p4 + (size_t)b * L4 * 4; nshift = 7; off = L3;         // n=128
    } else {
        s = 32.0f; lo = 128.0f; hi = INFINITY;
        pred = p5 + (size_t)b * L5 * 4; nshift = 6; off = L3 + L4;    // n=64
    }
    const int nmask = (1 << nshift) - 1;

    const int l0   = locb - off;             // level-local block start
    const int lidx = l0 + 2 * tid;           // this thread's first location
    const int row  = lidx >> nshift;
    const int col  = lidx & nmask;           // 2-aligned -> both in one row
    // Analytic coords: (k+0.5)*2^m exact in fp32 -> bitwise equal to ref.
    const float y  = ((float)row + 0.5f) * s;
    const float xA = ((float)col + 0.5f) * s;
    const float xB = xA + s;

    // Analytic y-band of the whole block (1/2/4 rows).
    const float ylo = ((float)(l0 >> nshift)         + 0.5f) * s;
    const float yhi = ((float)((l0 + 255) >> nshift) + 0.5f) * s;

    // Prefetch predictions (2 x LDG.128, independent of the barrier).
    const float4 pA = reinterpret_cast<const float4*>(pred)[lidx];
    const float4 pB = reinterpret_cast<const float4*>(pred)[lidx + 1];

    // ---- Phase 1: 4 warps build compacted per-warp shortlists ----
    {
        const int w    = tid >> 5;
        const int lane = tid & 31;
        const float* g = gt + ((size_t)(b * NGT + tid)) * 5;
        const float bx0 = g[0], by0 = g[1], bx1 = g[2], by1 = g[3];
        // Valid-center window: x in (max(x0,x1-hi), min(x1,x0+hi)), same in y.
        const float xl = fmaxf(bx0, bx1 - hi), xh = fminf(bx1, bx0 + hi);
        const float yl = fmaxf(by0, by1 - hi), yh = fminf(by1, by0 + hi);
        const bool cand = (xh > xl) && (yh > ylo) && (yl < yhi);
        const unsigned mask = __ballot_sync(0xFFFFFFFFu, cand);
        if (cand) {
            const int slot = (w << 5) + __popc(mask & ((1u << lane) - 1u));
            sbox[slot] = make_float4(bx0, by0, bx1, by1);
            const float mmv = 1e8f - (bx1 - bx0) * (by1 - by0);
            // mm bits (positive float, order-isomorphic) | first-index tie | slot.
            skey[slot] = ((unsigned long long)__float_as_uint(mmv) << 32) |
                         ((unsigned)(NGT - 1 - tid) << 8) | (unsigned)slot;
        }
        if (lane == 0) swc[w] = __popc(mask);
    }
    __syncthreads();

    // ---- Phase 2: scan compacted segments, 2 x-positions per entry ----
    unsigned long long bestA = 0ull, bestB = 0ull;
    #pragma unroll
    for (int w = 0; w < 4; ++w) {
        const int cnt  = swc[w];
        const int base = w << 5;
        for (int k = 0; k < cnt; ++k) {
            const float4 bx = sbox[base + k];
            const float t  = y - bx.y;
            const float bt = bx.w - y;
            const float vmin = fminf(t, bt);
            const float vmax = fmaxf(t, bt);
            const unsigned long long key = skey[base + k];
            {
                const float l = xA - bx.x, r = bx.z - xA;
                const float pmin = fminf(fminf(l, r), vmin);
                const float pmax = fmaxf(fmaxf(l, r), vmax);
                if (pmin > 0.0f && pmax > lo && pmax < hi && key > bestA)
                    bestA = key;
            }
            {
                const float l = xB - bx.x, r = bx.z - xB;
                const float pmin = fminf(fminf(l, r), vmin);
                const float pmax = fmaxf(fmaxf(l, r), vmax);
                if (pmin > 0.0f && pmax > lo && pmax < hi && key > bestB)
                    bestB = key;
            }
        }
    }

    // ---- Phase 3: finalize both locations ----
    float v[18];
    const float inv_s = 1.0f / s;

    #pragma unroll
    for (int q = 0; q < 2; ++q) {
        const unsigned long long best = q ? bestB : bestA;
        const float x = q ? xB : xA;
        float* o = v + q * 9;
        if (best == 0ull) {
            o[0] = o[1] = o[2] = o[3] = -1.0f;
            o[4] = -1.0f;
        } else {
            const float4 bx = sbox[best & 0xFFu];
            const float d0 = (x - bx.x) * inv_s;
            const float d1 = (y - bx.y) * inv_s;
            const float d2 = (bx.z - x) * inv_s;
            const float d3 = (bx.w - y) * inv_s;
            const float lrmin = fminf(d0, d2), lrmax = fmaxf(d0, d2);
            const float tbmin = fminf(d1, d3), tbmax = fmaxf(d1, d3);
            const float ratio = fminf(lrmin, tbmin) / (fmaxf(lrmax, tbmax) + 1e-6f);
            o[0] = d0; o[1] = d1; o[2] = d2; o[3] = d3;
            o[4] = sqrtf(fmaxf(ratio, 0.0f));
        }
        const float4 p = q ? pB : pA;
        o[5] = fmaxf(x - fmaxf(p.x, 0.0f) * s, 0.0f);
        o[6] = fmaxf(y - fmaxf(p.y, 0.0f) * s, 0.0f);
        o[7] = fmaxf(x + fmaxf(p.z, 0.0f) * s, 0.0f);
        o[8] = fmaxf(y + fmaxf(p.w, 0.0f) * s, 0.0f);
    }

    // 18 contiguous floats (72B, 8B-aligned): 4 x STG.128 + 1 x STG.64 via
    // float2 writes the compiler can merge; keep explicit float2 for safety.
    const size_t i0 = (size_t)b * LTOT + off + lidx;
    float2* o2 = reinterpret_cast<float2*>(out + i0 * 9);
    #pragma unroll
    for (int k = 0; k < 9; ++k)
        o2[k] = make_float2(v[2 * k], v[2 * k + 1]);
}

extern "C" void kernel_launch(void* const* d_in, const int* in_sizes, int n_in,
                              void* d_out, int out_size) {
    const float* gt = (const float*)d_in[3];
    const float* p3 = (const float*)d_in[4];
    const float* p4 = (const float*)d_in[5];
    const float* p5 = (const float*)d_in[6];
    float* out = (float*)d_out;

    const int blocks = NB * LTOT / 256;   // 672
    fcos_fused<<<blocks, 128>>>(gt, p3, p4, p5, out);
}